// round 1
// baseline (speedup 1.0000x reference)
#include <cuda_runtime.h>
#include <math.h>

// ---------------- problem constants ----------------
#define BATCH 32
#define CCH   768
#define TMAX  1022
#define DDIM  64
#define MEMB  512
#define TP    511
#define NVEC  (BATCH * TP)        // 16352
#define NPART (NVEC / 8)          // 2044 (VQ blocks: 8 warps/block, 1 vec/warp)

// ---------------- device scratch (static, no runtime alloc) ----------------
__device__ float g_bufA[(size_t)BATCH * CCH * TMAX];   // ~100.5 MB
__device__ float g_bufB[(size_t)BATCH * CCH * TMAX];   // ~100.5 MB
__device__ float g_z[(size_t)NVEC * DDIM];             // [B*Tp, 64]
__device__ float g_Et[DDIM * MEMB];                    // embedding transposed [64][512]
__device__ float g_esq[MEMB];                          // ||e||^2
__device__ int   g_counts[MEMB];
__device__ float g_partial[NPART];

// ============================================================
// Implicit-GEMM conv1d + BN + ReLU.
//   Y[b, co, t] = relu( BN( sum_{ci,k} W[co,ci,k] * X[b,ci,t*S + k - P] ) )
// GEMM view: M = 768 (co), N = Tout (per batch), Kdim = Cin*K.
// Tile 128x128x8, 256 threads, 8x8 accum per thread.
// ============================================================
template<int K, int STRIDE, int PAD>
__global__ __launch_bounds__(256) void conv_bn_relu(
    const float* __restrict__ X, const float* __restrict__ W,
    const float* __restrict__ gamma, const float* __restrict__ beta,
    const float* __restrict__ mean,  const float* __restrict__ var,
    float* __restrict__ Y, int Cin, int Tin, int Tout)
{
    const int Kdim = Cin * K;            // multiple of 8 for all layers
    __shared__ float As[8][128];         // W tile, transposed: As[p][m]
    __shared__ float Bs[8][128];         // X tile: Bs[p][n]

    const int tid = threadIdx.x;
    const int b   = blockIdx.z;
    const int m0  = blockIdx.y * 128;    // co tile
    const int t0  = blockIdx.x * 128;    // t tile

    const float* Xb = X + (size_t)b * Cin * Tin;

    float acc[8][8];
    #pragma unroll
    for (int i = 0; i < 8; i++)
        #pragma unroll
        for (int j = 0; j < 8; j++) acc[i][j] = 0.f;

    const int a_row = tid >> 1;          // 0..127 (m)
    const int a_col = (tid & 1) * 4;     // 0 or 4 (p)
    const int b_p   = tid >> 5;          // 0..7   (p)
    const int b_n0  = (tid & 31) * 4;    // n base

    const int tx = tid & 15;             // n micro-tile
    const int ty = tid >> 4;             // m micro-tile

    for (int p0 = 0; p0 < Kdim; p0 += 8) {
        // --- load W tile (float4, Kdim % 8 == 0 so aligned) ---
        float4 wv = *reinterpret_cast<const float4*>(
            W + (size_t)(m0 + a_row) * Kdim + p0 + a_col);
        As[a_col + 0][a_row] = wv.x;
        As[a_col + 1][a_row] = wv.y;
        As[a_col + 2][a_row] = wv.z;
        As[a_col + 3][a_row] = wv.w;

        // --- load X tile with implicit im2col + bounds (padding) ---
        {
            const int p  = p0 + b_p;
            const int ci = p / K;
            const int k  = p - ci * K;
            const float* Xrow = Xb + (size_t)ci * Tin;
            #pragma unroll
            for (int j = 0; j < 4; j++) {
                const int n   = b_n0 + j;
                const int tin = (t0 + n) * STRIDE + k - PAD;
                float v = 0.f;
                if (tin >= 0 && tin < Tin) v = Xrow[tin];
                Bs[b_p][n] = v;
            }
        }
        __syncthreads();

        #pragma unroll
        for (int kk = 0; kk < 8; kk++) {
            float4 a0 = *reinterpret_cast<const float4*>(&As[kk][ty * 8]);
            float4 a1 = *reinterpret_cast<const float4*>(&As[kk][ty * 8 + 4]);
            float4 c0 = *reinterpret_cast<const float4*>(&Bs[kk][tx * 8]);
            float4 c1 = *reinterpret_cast<const float4*>(&Bs[kk][tx * 8 + 4]);
            float ar[8] = {a0.x, a0.y, a0.z, a0.w, a1.x, a1.y, a1.z, a1.w};
            float br[8] = {c0.x, c0.y, c0.z, c0.w, c1.x, c1.y, c1.z, c1.w};
            #pragma unroll
            for (int i = 0; i < 8; i++)
                #pragma unroll
                for (int j = 0; j < 8; j++)
                    acc[i][j] = fmaf(ar[i], br[j], acc[i][j]);
        }
        __syncthreads();
    }

    // --- fused BN + ReLU epilogue ---
    #pragma unroll
    for (int i = 0; i < 8; i++) {
        const int co = m0 + ty * 8 + i;                 // M = 768 = 6*128 exact
        const float inv = gamma[co] * rsqrtf(var[co] + 1e-5f);
        const float sh  = beta[co] - mean[co] * inv;
        float* Yrow = Y + ((size_t)b * CCH + co) * Tout;
        #pragma unroll
        for (int j = 0; j < 8; j++) {
            const int t = t0 + tx * 8 + j;
            if (t < Tout) {
                float v = fmaf(acc[i][j], inv, sh);
                Yrow[t] = v > 0.f ? v : 0.f;
            }
        }
    }
}

// ============================================================
// conv6 (1x1, 768->64) + bias, fused transpose: Z[b*Tp + t][d]
// One block: 64 t x 64 d for one batch. 256 threads, 4x4 per thread.
// ============================================================
__global__ __launch_bounds__(256) void conv6_kernel(
    const float* __restrict__ X, const float* __restrict__ W6,
    const float* __restrict__ b6, float* __restrict__ Z)
{
    __shared__ float Xs[64][65];   // [ci][t]
    __shared__ float Ws[64][65];   // [d][ci]
    const int tid = threadIdx.x;
    const int b   = blockIdx.y;
    const int t0  = blockIdx.x * 64;

    const int tdx = tid & 15;      // d group
    const int ttx = tid >> 4;      // t group

    float acc[4][4];
    #pragma unroll
    for (int i = 0; i < 4; i++)
        #pragma unroll
        for (int j = 0; j < 4; j++) acc[i][j] = 0.f;

    const int lt = tid & 63;
    const int lr = tid >> 6;       // 0..3

    for (int c0 = 0; c0 < CCH; c0 += 64) {
        #pragma unroll
        for (int r = 0; r < 16; r++) {
            const int ci = lr + r * 4;
            const int t  = t0 + lt;
            Xs[ci][lt] = (t < TP) ? X[((size_t)b * CCH + c0 + ci) * TP + t] : 0.f;
            const int d  = lr + r * 4;
            Ws[d][lt] = W6[(size_t)d * CCH + c0 + lt];
        }
        __syncthreads();

        #pragma unroll 8
        for (int ci = 0; ci < 64; ci++) {
            float w[4], x[4];
            #pragma unroll
            for (int i = 0; i < 4; i++) w[i] = Ws[tdx * 4 + i][ci];
            #pragma unroll
            for (int j = 0; j < 4; j++) x[j] = Xs[ci][ttx * 4 + j];
            #pragma unroll
            for (int i = 0; i < 4; i++)
                #pragma unroll
                for (int j = 0; j < 4; j++)
                    acc[i][j] = fmaf(w[i], x[j], acc[i][j]);
        }
        __syncthreads();
    }

    #pragma unroll
    for (int i = 0; i < 4; i++) {
        const int d = tdx * 4 + i;
        const float bias = b6[d];
        #pragma unroll
        for (int j = 0; j < 4; j++) {
            const int t = t0 + ttx * 4 + j;
            if (t < TP)
                Z[((size_t)(b * TP + t)) * DDIM + d] = acc[i][j] + bias;
        }
    }
}

// ============================================================
// VQ prep: transpose embedding, compute ||e||^2, zero counts.
// ============================================================
__global__ void prep_vq(const float* __restrict__ E)
{
    const int e = threadIdx.x;     // 512 threads
    float s = 0.f;
    #pragma unroll
    for (int d = 0; d < DDIM; d++) {
        const float v = E[(size_t)e * DDIM + d];
        s = fmaf(v, v, s);
        g_Et[d * MEMB + e] = v;
    }
    g_esq[e] = s;
    g_counts[e] = 0;
}

// ============================================================
// VQ: one warp per vector. argmin_e ( ||e||^2 - 2 x.e ), first-min ties.
// Writes q_st = z + (E[idx]-z), per-block loss partial, counts histogram.
// ============================================================
__global__ __launch_bounds__(256) void vq_kernel(
    const float* __restrict__ Z, const float* __restrict__ E,
    float* __restrict__ out)
{
    __shared__ float zsh[8][64];
    __shared__ float pw[8];
    const int tid  = threadIdx.x;
    const int w    = tid >> 5;
    const int lane = tid & 31;
    const int vec  = blockIdx.x * 8 + w;   // always < NVEC (2044*8 exact)

    zsh[w][lane]      = Z[(size_t)vec * 64 + lane];
    zsh[w][lane + 32] = Z[(size_t)vec * 64 + lane + 32];
    __syncwarp();

    float best = 3.4e38f;
    int   bidx = 0;
    #pragma unroll
    for (int i = 0; i < 16; i++) {
        const int e = lane + 32 * i;
        float dot = 0.f;
        #pragma unroll
        for (int d = 0; d < 64; d++)
            dot = fmaf(zsh[w][d], g_Et[d * MEMB + e], dot);
        const float dist = g_esq[e] - 2.f * dot;
        if (dist < best) { best = dist; bidx = e; }   // strict < keeps lowest e
    }
    #pragma unroll
    for (int off = 16; off > 0; off >>= 1) {
        const float ob = __shfl_down_sync(0xFFFFFFFFu, best, off);
        const int   oi = __shfl_down_sync(0xFFFFFFFFu, bidx, off);
        if (ob < best || (ob == best && oi < bidx)) { best = ob; bidx = oi; }
    }
    bidx = __shfl_sync(0xFFFFFFFFu, bidx, 0);

    float lsum = 0.f;
    #pragma unroll
    for (int h = 0; h < 2; h++) {
        const int d  = lane + 32 * h;
        const float zv = zsh[w][d];
        const float q  = E[(size_t)bidx * 64 + d];
        out[(size_t)vec * 64 + d] = zv + (q - zv);    // straight-through
        const float diff = zv - q;
        lsum = fmaf(diff, diff, lsum);
    }
    #pragma unroll
    for (int off = 16; off > 0; off >>= 1)
        lsum += __shfl_down_sync(0xFFFFFFFFu, lsum, off);

    if (lane == 0) {
        pw[w] = lsum;
        atomicAdd(&g_counts[bidx], 1);
    }
    __syncthreads();
    if (tid == 0) {
        float s = 0.f;
        #pragma unroll
        for (int i = 0; i < 8; i++) s += pw[i];
        g_partial[blockIdx.x] = s;
    }
}

// ============================================================
// Finalize: loss = 0.25 * mean((z-q)^2); perplexity from counts.
// ============================================================
__global__ __launch_bounds__(1024) void finalize_kernel(float* __restrict__ out)
{
    __shared__ float sh[1024];
    const int tid = threadIdx.x;

    float s = 0.f;
    for (int i = tid; i < NPART; i += 1024) s += g_partial[i];
    sh[tid] = s; __syncthreads();
    for (int off = 512; off > 0; off >>= 1) {
        if (tid < off) sh[tid] += sh[tid + off];
        __syncthreads();
    }
    const float total = sh[0];
    __syncthreads();

    float h = 0.f;
    if (tid < MEMB) {
        const float p = (float)g_counts[tid] / (float)NVEC;
        h = p * logf(p + 1e-10f);
    }
    sh[tid] = h; __syncthreads();
    for (int off = 512; off > 0; off >>= 1) {
        if (tid < off) sh[tid] += sh[tid + off];
        __syncthreads();
    }
    if (tid == 0) {
        out[(size_t)NVEC * DDIM]     = 0.25f * total / (float)((size_t)NVEC * DDIM);
        out[(size_t)NVEC * DDIM + 1] = expf(-sh[0]);
    }
}

// ============================================================
// launch
// ============================================================
extern "C" void kernel_launch(void* const* d_in, const int* in_sizes, int n_in,
                              void* d_out, int out_size)
{
    const float* mels  = (const float*)d_in[0];
    const float* w1    = (const float*)d_in[1];
    const float* w2    = (const float*)d_in[2];
    const float* w3    = (const float*)d_in[3];
    const float* w4    = (const float*)d_in[4];
    const float* w5    = (const float*)d_in[5];
    const float* w6    = (const float*)d_in[6];
    const float* b6    = (const float*)d_in[7];
    const float* gamma = (const float*)d_in[8];
    const float* beta  = (const float*)d_in[9];
    const float* mean  = (const float*)d_in[10];
    const float* var   = (const float*)d_in[11];
    const float* emb   = (const float*)d_in[12];
    float* out = (float*)d_out;

    float *bufA, *bufB, *zbuf;
    cudaGetSymbolAddress((void**)&bufA, g_bufA);
    cudaGetSymbolAddress((void**)&bufB, g_bufB);
    cudaGetSymbolAddress((void**)&zbuf, g_z);

    const dim3 blk(256);
    // conv1: [32,80,1024] -> [32,768,1022], K3 s1 p0, BN0
    conv_bn_relu<3,1,0><<<dim3(8, 6, BATCH), blk>>>(
        mels, w1, gamma, beta, mean, var, bufA, 80, 1024, 1022);
    // conv2: K3 s1 p1, BN1
    conv_bn_relu<3,1,1><<<dim3(8, 6, BATCH), blk>>>(
        bufA, w2, gamma + CCH, beta + CCH, mean + CCH, var + CCH,
        bufB, CCH, 1022, 1022);
    // conv3: K4 s2 p1 -> T=511, BN2
    conv_bn_relu<4,2,1><<<dim3(4, 6, BATCH), blk>>>(
        bufB, w3, gamma + 2*CCH, beta + 2*CCH, mean + 2*CCH, var + 2*CCH,
        bufA, CCH, 1022, 511);
    // conv4: K3 s1 p1, BN3
    conv_bn_relu<3,1,1><<<dim3(4, 6, BATCH), blk>>>(
        bufA, w4, gamma + 3*CCH, beta + 3*CCH, mean + 3*CCH, var + 3*CCH,
        bufB, CCH, 511, 511);
    // conv5: K3 s1 p1, BN4
    conv_bn_relu<3,1,1><<<dim3(4, 6, BATCH), blk>>>(
        bufB, w5, gamma + 4*CCH, beta + 4*CCH, mean + 4*CCH, var + 4*CCH,
        bufA, CCH, 511, 511);
    // conv6 1x1 + bias + transpose -> z [B*Tp, 64]
    conv6_kernel<<<dim3(8, BATCH), blk>>>(bufA, w6, b6, zbuf);
    // VQ
    prep_vq<<<1, MEMB>>>(emb);
    vq_kernel<<<NPART, blk>>>(zbuf, emb, out);
    finalize_kernel<<<1, 1024>>>(out);
}